// round 4
// baseline (speedup 1.0000x reference)
#include <cuda_runtime.h>

#define Dd 256
#define Nn 1024
#define Mm 1024
#define RG 8                   // rows per tile
#define CTW 256                // cols per tile
#define NTILE 512              // (1024/8) * (1024/256)
#define NGRP 256               // 4-row column-partial groups
#define GRID 296               // 2 blocks per SM, guaranteed co-resident

typedef unsigned long long u64;
typedef unsigned int u32;

// Scratch (static __device__ — no runtime allocation)
__device__ float g_S[Nn * Mm];            // score matrix s = -L1dist (4 MB)
__device__ float g_pm[Mm * NGRP];         // col partial max, transposed [col][group]
__device__ float g_ps[Mm * NGRP];         // col partial expsum
__device__ float g_cm[Mm], g_cinv[Mm];    // column max, 1/colsum
__device__ float g_num[Nn], g_den[Nn];    // per-row final partials
__device__ u32 g_tile, g_barA, g_barB, g_barC;

#define FMA2(o, a, b, c) asm("fma.rn.f32x2 %0, %1, %2, %3;" : "=l"(o) : "l"(a), "l"(b), "l"(c))
#define ADD2(o, a, b)    asm("add.rn.f32x2 %0, %1, %2;"     : "=l"(o) : "l"(a), "l"(b))

__device__ __forceinline__ float lo32(u64 v) { return __uint_as_float((u32)v); }
__device__ __forceinline__ float hi32(u64 v) { return __uint_as_float((u32)(v >> 32)); }

__device__ __forceinline__ u32 ld_acq(const u32* p) {
    u32 v;
    asm volatile("ld.acquire.gpu.u32 %0, [%1];" : "=r"(v) : "l"(p));
    return v;
}

__device__ __forceinline__ float warpMax(float v) {
    #pragma unroll
    for (int o = 16; o; o >>= 1) v = fmaxf(v, __shfl_xor_sync(0xffffffffu, v, o));
    return v;
}
__device__ __forceinline__ float warpSum(float v) {
    #pragma unroll
    for (int o = 16; o; o >>= 1) v += __shfl_xor_sync(0xffffffffu, v, o);
    return v;
}

// Grid barrier: arrive (release) and optional wait (acquire).
__device__ __forceinline__ void bar_arrive(u32* ctr) {
    __syncthreads();
    __threadfence();
    if (threadIdx.x == 0) atomicAdd(ctr, 1u);
}
__device__ __forceinline__ void bar_wait(u32* ctr, u32 target) {
    if (threadIdx.x == 0) {
        while (ld_acq(ctr) < target) __nanosleep(64);
    }
    __syncthreads();
}

__global__ void k_init() {
    if (threadIdx.x == 0) { g_tile = 0; g_barA = 0; g_barB = 0; g_barC = 0; }
}

__global__ __launch_bounds__(256, 2) void k_fused(
    const float* __restrict__ zx, const float* __restrict__ zy,
    float* __restrict__ out)
{
    __shared__ __align__(16) float2 xs[Dd][RG];   // duplicated (x,x) pairs, 16KB
    __shared__ u32 sh_tile;
    __shared__ float shn[8], shd[8];

    const int t = threadIdx.x;
    const int bid = blockIdx.x;
    const int w = t >> 5, lane = t & 31;

    const u64 NEG1 = 0xBF800000BF800000ULL;
    const u64 ABSM = 0x7FFFFFFF7FFFFFFFULL;

    // ================= Phase 1: scores + column partials (tile stealing) =================
    while (true) {
        __syncthreads();                       // protect xs/sh_tile from prior iter
        if (t == 0) sh_tile = atomicAdd(&g_tile, 1u);
        __syncthreads();
        const u32 tile = sh_tile;
        if (tile >= NTILE) break;

        const int rt = tile >> 2, ct = tile & 3;
        const int i0 = rt * RG, j0 = ct * CTW;

        for (int idx = t; idx < Dd * RG; idx += 256) {
            int d = idx >> 3, r = idx & 7;
            float v = zx[d * Nn + i0 + r];
            xs[d][r] = make_float2(v, v);
        }
        __syncthreads();

        const int cp = t & 127;                // col pair -> cols j0+2cp, j0+2cp+1
        const int rp = t >> 7;                 // row half -> rows rp*4 .. rp*4+3

        u64 acc0 = 0, acc1 = 0, acc2 = 0, acc3 = 0;
        const u64* yb = reinterpret_cast<const u64*>(zy) + (j0 >> 1) + cp; // stride 512/d

        u64 yreg[4];
        #pragma unroll
        for (int p = 0; p < 4; ++p) yreg[p] = yb[(size_t)p * 512];

        for (int d = 0; d < Dd; d += 4) {
            #pragma unroll
            for (int q = 0; q < 4; ++q) {
                const u64 yc = yreg[q];
                const int dn = d + q + 4;
                if (dn < Dd) yreg[q] = yb[(size_t)dn * 512];
                ulonglong2 xa = *reinterpret_cast<const ulonglong2*>(&xs[d + q][rp * 4]);
                ulonglong2 xb = *reinterpret_cast<const ulonglong2*>(&xs[d + q][rp * 4 + 2]);
                u64 d0, d1, d2, d3;
                FMA2(d0, yc, NEG1, xa.x);
                FMA2(d1, yc, NEG1, xa.y);
                FMA2(d2, yc, NEG1, xb.x);
                FMA2(d3, yc, NEG1, xb.y);
                d0 &= ABSM; d1 &= ABSM; d2 &= ABSM; d3 &= ABSM;
                ADD2(acc0, acc0, d0);
                ADD2(acc1, acc1, d1);
                ADD2(acc2, acc2, d2);
                ADD2(acc3, acc3, d3);
            }
        }

        // Epilogue: store s = -dist, and per-4-row column partials (transposed).
        float sl[4], sh4[4];
        sl[0] = -lo32(acc0); sh4[0] = -hi32(acc0);
        sl[1] = -lo32(acc1); sh4[1] = -hi32(acc1);
        sl[2] = -lo32(acc2); sh4[2] = -hi32(acc2);
        sl[3] = -lo32(acc3); sh4[3] = -hi32(acc3);

        const int ib = i0 + rp * 4;
        const int j = j0 + 2 * cp;
        #pragma unroll
        for (int r = 0; r < 4; ++r)
            *reinterpret_cast<float2*>(g_S + (size_t)(ib + r) * Mm + j) =
                make_float2(sl[r], sh4[r]);

        float m0 = fmaxf(fmaxf(sl[0], sl[1]), fmaxf(sl[2], sl[3]));
        float m1 = fmaxf(fmaxf(sh4[0], sh4[1]), fmaxf(sh4[2], sh4[3]));
        float e0 = __expf(sl[0] - m0) + __expf(sl[1] - m0) +
                   __expf(sl[2] - m0) + __expf(sl[3] - m0);
        float e1 = __expf(sh4[0] - m1) + __expf(sh4[1] - m1) +
                   __expf(sh4[2] - m1) + __expf(sh4[3] - m1);

        const int g = rt * 2 + rp;
        g_pm[(size_t)j * NGRP + g] = m0;
        g_pm[(size_t)(j + 1) * NGRP + g] = m1;
        g_ps[(size_t)j * NGRP + g] = e0;
        g_ps[(size_t)(j + 1) * NGRP + g] = e1;
    }

    bar_arrive(&g_barA);
    const bool worker = (bid < 128);           // phases 2/3 use blocks 0..127

    if (worker) {
        bar_wait(&g_barA, GRID);

        // ================= Phase 2: combine 256 column partials (warp per column) ========
        const int jcol = bid * 8 + w;          // 0..1023
        {
            const float4* pm = reinterpret_cast<const float4*>(g_pm + (size_t)jcol * NGRP);
            const float4* ps = reinterpret_cast<const float4*>(g_ps + (size_t)jcol * NGRP);
            float4 m4a = pm[lane * 2], m4b = pm[lane * 2 + 1];
            float m = fmaxf(fmaxf(fmaxf(m4a.x, m4a.y), fmaxf(m4a.z, m4a.w)),
                            fmaxf(fmaxf(m4b.x, m4b.y), fmaxf(m4b.z, m4b.w)));
            m = warpMax(m);
            float4 s4a = ps[lane * 2], s4b = ps[lane * 2 + 1];
            float s = s4a.x * __expf(m4a.x - m) + s4a.y * __expf(m4a.y - m) +
                      s4a.z * __expf(m4a.z - m) + s4a.w * __expf(m4a.w - m) +
                      s4b.x * __expf(m4b.x - m) + s4b.y * __expf(m4b.y - m) +
                      s4b.z * __expf(m4b.z - m) + s4b.w * __expf(m4b.w - m);
            s = warpSum(s);
            if (lane == 0) { g_cm[jcol] = m; g_cinv[jcol] = 1.0f / s; }
        }
    }

    bar_arrive(&g_barB);

    if (worker) {
        bar_wait(&g_barB, GRID);

        // ================= Phase 3: warp-per-row final partials ==========================
        const int i = bid * 8 + w;             // 0..1023
        const float4* row = reinterpret_cast<const float4*>(g_S + (size_t)i * Mm);

        float4 s[8];
        float m = -3.4e38f;
        #pragma unroll
        for (int q = 0; q < 8; ++q) {
            s[q] = row[q * 32 + lane];
            m = fmaxf(m, fmaxf(fmaxf(s[q].x, s[q].y), fmaxf(s[q].z, s[q].w)));
        }
        m = warpMax(m);

        float4 e[8];
        float rs = 0.f;
        #pragma unroll
        for (int q = 0; q < 8; ++q) {
            e[q].x = __expf(s[q].x - m); e[q].y = __expf(s[q].y - m);
            e[q].z = __expf(s[q].z - m); e[q].w = __expf(s[q].w - m);
            rs += e[q].x + e[q].y + e[q].z + e[q].w;
        }
        rs = warpSum(rs);
        const float rinv = 1.0f / rs;

        float num = 0.f, den = 0.f;
        #pragma unroll
        for (int q = 0; q < 8; ++q) {
            float4 cm = reinterpret_cast<const float4*>(g_cm)[q * 32 + lane];
            float4 ci = reinterpret_cast<const float4*>(g_cinv)[q * 32 + lane];
            {
                float a = e[q].x * rinv, b = __expf(s[q].x - cm.x) * ci.x;
                float u = a + b - a * b; num += u * s[q].x; den += u;
            }
            {
                float a = e[q].y * rinv, b = __expf(s[q].y - cm.y) * ci.y;
                float u = a + b - a * b; num += u * s[q].y; den += u;
            }
            {
                float a = e[q].z * rinv, b = __expf(s[q].z - cm.z) * ci.z;
                float u = a + b - a * b; num += u * s[q].z; den += u;
            }
            {
                float a = e[q].w * rinv, b = __expf(s[q].w - cm.w) * ci.w;
                float u = a + b - a * b; num += u * s[q].w; den += u;
            }
        }
        num = warpSum(num);
        den = warpSum(den);
        if (lane == 0) { g_num[i] = num; g_den[i] = den; }
    }

    bar_arrive(&g_barC);
    if (bid != 0) return;

    // ================= Phase 4: block 0 deterministic scalar combine =====================
    bar_wait(&g_barC, GRID);
    float num = 0.f, den = 0.f;
    #pragma unroll
    for (int p = t; p < Nn; p += 256) { num += g_num[p]; den += g_den[p]; }
    num = warpSum(num); den = warpSum(den);
    if (lane == 0) { shn[w] = num; shd[w] = den; }
    __syncthreads();
    if (w == 0) {
        float n = (lane < 8) ? shn[lane] : 0.f;
        float d = (lane < 8) ? shd[lane] : 0.f;
        n = warpSum(n); d = warpSum(d);
        if (lane == 0) out[0] = n / d;
    }
}

extern "C" void kernel_launch(void* const* d_in, const int* in_sizes, int n_in,
                              void* d_out, int out_size)
{
    const float* zx = (const float*)d_in[0];
    const float* zy = (const float*)d_in[1];
    float* out = (float*)d_out;

    k_init<<<1, 32>>>();
    k_fused<<<GRID, 256>>>(zx, zy, out);
}

// round 5
// speedup vs baseline: 1.0690x; 1.0690x over previous
#include <cuda_runtime.h>

#define Dd 256
#define Nn 1024
#define Mm 1024
#define RG 8                  // rows per K1 tile
#define CT 128                // cols per K1 tile
#define NGRP 256              // 4-row column-partial groups (1024/4)
#define K3_BLOCKS 128

typedef unsigned long long u64;
typedef unsigned int u32;

// Scratch (static __device__ — no runtime allocation)
__device__ float g_S[Nn * Mm];            // score matrix s = -L1dist (4 MB)
__device__ float g_pm[Mm * NGRP];         // col partial max, transposed [col][group]
__device__ float g_ps[Mm * NGRP];         // col partial expsum
__device__ float g_cm[Mm], g_cinv[Mm];    // column max, 1/colsum
__device__ float g_num[Nn], g_den[Nn];    // per-row final partials
__device__ u32 g_done = 0;                // k3 last-block counter (self-resetting)

#define FMA2(o, a, b, c) asm("fma.rn.f32x2 %0, %1, %2, %3;" : "=l"(o) : "l"(a), "l"(b), "l"(c))
#define ADD2(o, a, b)    asm("add.rn.f32x2 %0, %1, %2;"     : "=l"(o) : "l"(a), "l"(b))

__device__ __forceinline__ float lo32(u64 v) { return __uint_as_float((u32)v); }
__device__ __forceinline__ float hi32(u64 v) { return __uint_as_float((u32)(v >> 32)); }

__device__ __forceinline__ float warpMax(float v) {
    #pragma unroll
    for (int o = 16; o; o >>= 1) v = fmaxf(v, __shfl_xor_sync(0xffffffffu, v, o));
    return v;
}
__device__ __forceinline__ float warpSum(float v) {
    #pragma unroll
    for (int o = 16; o; o >>= 1) v += __shfl_xor_sync(0xffffffffu, v, o);
    return v;
}

// ===================== K1: scores + per-4-row-group column partials =====================
// 1024 blocks (128 row-groups x 8 col-tiles), 128 threads, 8 blocks/SM resident.
// Thread t: col pair cp = t&63 (cols j0+2cp, j0+2cp+1), row half rp = t>>6.
__global__ __launch_bounds__(128, 8) void k1_scores(
    const float* __restrict__ zx, const float* __restrict__ zy)
{
    __shared__ __align__(16) float2 xs[Dd][RG];   // duplicated (x,x) pairs, 16KB
    const int t = threadIdx.x;
    const int rg = blockIdx.x >> 3;
    const int ct = blockIdx.x & 7;
    const int i0 = rg * RG, j0 = ct * CT;

    for (int idx = t; idx < Dd * RG; idx += 128) {
        int d = idx >> 3, r = idx & 7;
        float v = zx[d * Nn + i0 + r];
        xs[d][r] = make_float2(v, v);
    }
    __syncthreads();

    const int cp = t & 63;
    const int rp = t >> 6;

    const u64 NEG1 = 0xBF800000BF800000ULL;
    const u64 ABSM = 0x7FFFFFFF7FFFFFFFULL;

    u64 acc0 = 0, acc1 = 0, acc2 = 0, acc3 = 0;
    const u64* yb = reinterpret_cast<const u64*>(zy) + (j0 >> 1) + cp;  // stride 512 per d

    u64 yr0 = yb[0];
    u64 yr1 = yb[512];
    u64 yr2 = yb[1024];
    u64 yr3 = yb[1536];

    for (int d = 0; d < Dd; d += 4) {
        #pragma unroll
        for (int q = 0; q < 4; ++q) {
            u64 yc;
            if (q == 0) { yc = yr0; if (d + 4 < Dd) yr0 = yb[(size_t)(d + 4) * 512]; }
            if (q == 1) { yc = yr1; if (d + 5 < Dd) yr1 = yb[(size_t)(d + 5) * 512]; }
            if (q == 2) { yc = yr2; if (d + 6 < Dd) yr2 = yb[(size_t)(d + 6) * 512]; }
            if (q == 3) { yc = yr3; if (d + 7 < Dd) yr3 = yb[(size_t)(d + 7) * 512]; }
            ulonglong2 xa = *reinterpret_cast<const ulonglong2*>(&xs[d + q][rp * 4]);
            ulonglong2 xb = *reinterpret_cast<const ulonglong2*>(&xs[d + q][rp * 4 + 2]);
            u64 d0, d1, d2, d3;
            FMA2(d0, yc, NEG1, xa.x);
            FMA2(d1, yc, NEG1, xa.y);
            FMA2(d2, yc, NEG1, xb.x);
            FMA2(d3, yc, NEG1, xb.y);
            d0 &= ABSM; d1 &= ABSM; d2 &= ABSM; d3 &= ABSM;
            ADD2(acc0, acc0, d0);
            ADD2(acc1, acc1, d1);
            ADD2(acc2, acc2, d2);
            ADD2(acc3, acc3, d3);
        }
    }

    // Epilogue: store s = -dist, and per-4-row column partials (transposed).
    float sl[4], sh[4];
    sl[0] = -lo32(acc0); sh[0] = -hi32(acc0);
    sl[1] = -lo32(acc1); sh[1] = -hi32(acc1);
    sl[2] = -lo32(acc2); sh[2] = -hi32(acc2);
    sl[3] = -lo32(acc3); sh[3] = -hi32(acc3);

    const int ib = i0 + rp * 4;
    const int j = j0 + 2 * cp;
    #pragma unroll
    for (int r = 0; r < 4; ++r)
        *reinterpret_cast<float2*>(g_S + (size_t)(ib + r) * Mm + j) = make_float2(sl[r], sh[r]);

    float m0 = fmaxf(fmaxf(sl[0], sl[1]), fmaxf(sl[2], sl[3]));
    float m1 = fmaxf(fmaxf(sh[0], sh[1]), fmaxf(sh[2], sh[3]));
    float e0 = __expf(sl[0] - m0) + __expf(sl[1] - m0) + __expf(sl[2] - m0) + __expf(sl[3] - m0);
    float e1 = __expf(sh[0] - m1) + __expf(sh[1] - m1) + __expf(sh[2] - m1) + __expf(sh[3] - m1);

    const int g = rg * 2 + rp;
    g_pm[(size_t)j * NGRP + g] = m0;
    g_pm[(size_t)(j + 1) * NGRP + g] = m1;
    g_ps[(size_t)j * NGRP + g] = e0;
    g_ps[(size_t)(j + 1) * NGRP + g] = e1;
}

// ===================== K2: combine 256 column partials (warp per column) =====================
__global__ __launch_bounds__(256) void k2_colcombine()
{
    const int w = threadIdx.x >> 5, lane = threadIdx.x & 31;
    const int j = blockIdx.x * 8 + w;
    const float4* pm = reinterpret_cast<const float4*>(g_pm + (size_t)j * NGRP);
    const float4* ps = reinterpret_cast<const float4*>(g_ps + (size_t)j * NGRP);

    float4 m4a = pm[lane * 2], m4b = pm[lane * 2 + 1];
    float m = fmaxf(fmaxf(fmaxf(m4a.x, m4a.y), fmaxf(m4a.z, m4a.w)),
                    fmaxf(fmaxf(m4b.x, m4b.y), fmaxf(m4b.z, m4b.w)));
    m = warpMax(m);

    float4 s4a = ps[lane * 2], s4b = ps[lane * 2 + 1];
    float s = s4a.x * __expf(m4a.x - m) + s4a.y * __expf(m4a.y - m) +
              s4a.z * __expf(m4a.z - m) + s4a.w * __expf(m4a.w - m) +
              s4b.x * __expf(m4b.x - m) + s4b.y * __expf(m4b.y - m) +
              s4b.z * __expf(m4b.z - m) + s4b.w * __expf(m4b.w - m);
    s = warpSum(s);

    if (lane == 0) { g_cm[j] = m; g_cinv[j] = 1.0f / s; }
}

// ===================== K3: warp-per-row final partials + last-block combine =====================
__global__ __launch_bounds__(256) void k3_rows(float* __restrict__ out)
{
    __shared__ float shn[8], shd[8];
    __shared__ u32 sh_last;
    const int t = threadIdx.x;
    const int w = t >> 5, lane = t & 31;
    const int i = blockIdx.x * 8 + w;
    const float4* row = reinterpret_cast<const float4*>(g_S + (size_t)i * Mm);

    float4 s[8];
    float m = -3.4e38f;
    #pragma unroll
    for (int q = 0; q < 8; ++q) {
        s[q] = row[q * 32 + lane];
        m = fmaxf(m, fmaxf(fmaxf(s[q].x, s[q].y), fmaxf(s[q].z, s[q].w)));
    }
    m = warpMax(m);

    float4 e[8];
    float rs = 0.f;
    #pragma unroll
    for (int q = 0; q < 8; ++q) {
        e[q].x = __expf(s[q].x - m); e[q].y = __expf(s[q].y - m);
        e[q].z = __expf(s[q].z - m); e[q].w = __expf(s[q].w - m);
        rs += e[q].x + e[q].y + e[q].z + e[q].w;
    }
    rs = warpSum(rs);
    const float rinv = 1.0f / rs;

    float num = 0.f, den = 0.f;
    #pragma unroll
    for (int q = 0; q < 8; ++q) {
        float4 cm = reinterpret_cast<const float4*>(g_cm)[q * 32 + lane];
        float4 ci = reinterpret_cast<const float4*>(g_cinv)[q * 32 + lane];
        {
            float a = e[q].x * rinv, b = __expf(s[q].x - cm.x) * ci.x;
            float u = a + b - a * b; num += u * s[q].x; den += u;
        }
        {
            float a = e[q].y * rinv, b = __expf(s[q].y - cm.y) * ci.y;
            float u = a + b - a * b; num += u * s[q].y; den += u;
        }
        {
            float a = e[q].z * rinv, b = __expf(s[q].z - cm.z) * ci.z;
            float u = a + b - a * b; num += u * s[q].z; den += u;
        }
        {
            float a = e[q].w * rinv, b = __expf(s[q].w - cm.w) * ci.w;
            float u = a + b - a * b; num += u * s[q].w; den += u;
        }
    }
    num = warpSum(num);
    den = warpSum(den);
    if (lane == 0) { g_num[i] = num; g_den[i] = den; }

    // ---- last-block deterministic combine ----
    __threadfence();
    __syncthreads();
    if (t == 0) sh_last = atomicAdd(&g_done, 1u);
    __syncthreads();
    if (sh_last != K3_BLOCKS - 1) return;

    __threadfence();   // acquire side: see all blocks' g_num/g_den
    float n2 = 0.f, d2 = 0.f;
    #pragma unroll
    for (int p = t; p < Nn; p += 256) { n2 += g_num[p]; d2 += g_den[p]; }
    n2 = warpSum(n2); d2 = warpSum(d2);
    if (lane == 0) { shn[w] = n2; shd[w] = d2; }
    __syncthreads();
    if (w == 0) {
        float n = (lane < 8) ? shn[lane] : 0.f;
        float d = (lane < 8) ? shd[lane] : 0.f;
        n = warpSum(n); d = warpSum(d);
        if (lane == 0) {
            out[0] = n / d;
            g_done = 0;          // self-reset for next graph replay
        }
    }
}

extern "C" void kernel_launch(void* const* d_in, const int* in_sizes, int n_in,
                              void* d_out, int out_size)
{
    const float* zx = (const float*)d_in[0];
    const float* zy = (const float*)d_in[1];
    float* out = (float*)d_out;

    k1_scores<<<(Nn / RG) * (Mm / CT), 128>>>(zx, zy);
    k2_colcombine<<<Mm / 8, 256>>>();
    k3_rows<<<K3_BLOCKS, 256>>>(out);
}

// round 6
// speedup vs baseline: 1.1752x; 1.0993x over previous
#include <cuda_runtime.h>

#define Dd 256
#define Nn 1024
#define Mm 1024
#define RG 8                  // rows per K1 tile
#define CT 128                // cols per K1 tile
#define NGRP 256              // 4-row column-partial groups (1024/4)
#define K3_BLOCKS 128

typedef unsigned long long u64;
typedef unsigned int u32;

// Scratch (static __device__ — no runtime allocation)
__device__ float g_S[Nn * Mm];            // score matrix s = -L1dist (4 MB)
__device__ float g_pm[Mm * NGRP];         // col partial max, transposed [col][group]
__device__ float g_ps[Mm * NGRP];         // col partial expsum
__device__ float g_cm[Mm], g_cinv[Mm];    // column max, 1/colsum
__device__ float g_num[Nn], g_den[Nn];    // per-row final partials
__device__ u32 g_done = 0;                // k3 last-block counter (self-resetting)

#define FMA2(o, a, b, c) asm("fma.rn.f32x2 %0, %1, %2, %3;" : "=l"(o) : "l"(a), "l"(b), "l"(c))
#define ADD2(o, a, b)    asm("add.rn.f32x2 %0, %1, %2;"     : "=l"(o) : "l"(a), "l"(b))

__device__ __forceinline__ float lo32(u64 v) { return __uint_as_float((u32)v); }
__device__ __forceinline__ float hi32(u64 v) { return __uint_as_float((u32)(v >> 32)); }

__device__ __forceinline__ float warpMax(float v) {
    #pragma unroll
    for (int o = 16; o; o >>= 1) v = fmaxf(v, __shfl_xor_sync(0xffffffffu, v, o));
    return v;
}
__device__ __forceinline__ float warpSum(float v) {
    #pragma unroll
    for (int o = 16; o; o >>= 1) v += __shfl_xor_sync(0xffffffffu, v, o);
    return v;
}

// ===================== K1: scores + per-4-row-group column partials =====================
// 1024 blocks (128 row-groups x 8 col-tiles), 128 threads.
// Thread t: col pair cp = t&63 (cols j0+2cp, j0+2cp+1), row half rp = t>>6 (4 rows).
// Mainloop: software-pipelined — x LDS double-buffered 2 iters ahead, y LDG 4-8 ahead.
__global__ __launch_bounds__(128, 8) void k1_scores(
    const float* __restrict__ zx, const float* __restrict__ zy)
{
    __shared__ __align__(16) float2 xs[Dd + 2][RG];   // +2 d-slots of padding for prefetch
    const int t = threadIdx.x;
    const int rg = blockIdx.x >> 3;
    const int ct = blockIdx.x & 7;
    const int i0 = rg * RG, j0 = ct * CT;

    for (int idx = t; idx < Dd * RG; idx += 128) {
        int d = idx >> 3, r = idx & 7;
        float v = zx[d * Nn + i0 + r];
        xs[d][r] = make_float2(v, v);
    }
    __syncthreads();

    const int cp = t & 63;
    const int rp4 = (t >> 6) * 4;

    const u64 NEG1 = 0xBF800000BF800000ULL;
    const u64 ABSM = 0x7FFFFFFF7FFFFFFFULL;

    u64 acc0 = 0, acc1 = 0, acc2 = 0, acc3 = 0;
    const u64* yb = reinterpret_cast<const u64*>(zy) + (j0 >> 1) + cp;  // stride 512 per d

    // y prefetch: one chunk (4 d) ahead
    u64 yr0 = yb[0], yr1 = yb[512], yr2 = yb[1024], yr3 = yb[1536];

    // x double buffers: X0 holds even-d, X1 holds odd-d (each 4 u64 = 4 rows duplicated)
    ulonglong2 x0a = *reinterpret_cast<const ulonglong2*>(&xs[0][rp4]);
    ulonglong2 x0b = *reinterpret_cast<const ulonglong2*>(&xs[0][rp4 + 2]);
    ulonglong2 x1a = *reinterpret_cast<const ulonglong2*>(&xs[1][rp4]);
    ulonglong2 x1b = *reinterpret_cast<const ulonglong2*>(&xs[1][rp4 + 2]);

    #define SUBITER(YC, XA, XB, DNEXT)                                           \
    {                                                                            \
        u64 d0, d1, d2, d3;                                                      \
        FMA2(d0, (YC), NEG1, (XA).x);                                            \
        FMA2(d1, (YC), NEG1, (XA).y);                                            \
        FMA2(d2, (YC), NEG1, (XB).x);                                            \
        FMA2(d3, (YC), NEG1, (XB).y);                                            \
        (XA) = *reinterpret_cast<const ulonglong2*>(&xs[(DNEXT)][rp4]);          \
        (XB) = *reinterpret_cast<const ulonglong2*>(&xs[(DNEXT)][rp4 + 2]);      \
        d0 &= ABSM; d1 &= ABSM; d2 &= ABSM; d3 &= ABSM;                          \
        ADD2(acc0, acc0, d0);                                                    \
        ADD2(acc1, acc1, d1);                                                    \
        ADD2(acc2, acc2, d2);                                                    \
        ADD2(acc3, acc3, d3);                                                    \
    }

    for (int c = 0; c < Dd / 4; ++c) {
        const int d = c * 4;
        // consume current chunk's y, start next chunk's loads (uniform branch)
        u64 yc0 = yr0, yc1 = yr1, yc2 = yr2, yc3 = yr3;
        if (c < Dd / 4 - 1) {
            yr0 = yb[(size_t)(d + 4) * 512];
            yr1 = yb[(size_t)(d + 5) * 512];
            yr2 = yb[(size_t)(d + 6) * 512];
            yr3 = yb[(size_t)(d + 7) * 512];
        }
        SUBITER(yc0, x0a, x0b, d + 2);   // uses d,   refills for d+2
        SUBITER(yc1, x1a, x1b, d + 3);   // uses d+1, refills for d+3
        SUBITER(yc2, x0a, x0b, d + 4);   // uses d+2, refills for d+4
        SUBITER(yc3, x1a, x1b, d + 5);   // uses d+3, refills for d+5 (pad-safe)
    }
    #undef SUBITER

    // Epilogue: store s = -dist, and per-4-row column partials (transposed).
    float sl[4], sh[4];
    sl[0] = -lo32(acc0); sh[0] = -hi32(acc0);
    sl[1] = -lo32(acc1); sh[1] = -hi32(acc1);
    sl[2] = -lo32(acc2); sh[2] = -hi32(acc2);
    sl[3] = -lo32(acc3); sh[3] = -hi32(acc3);

    const int ib = i0 + rp4;
    const int j = j0 + 2 * cp;
    #pragma unroll
    for (int r = 0; r < 4; ++r)
        *reinterpret_cast<float2*>(g_S + (size_t)(ib + r) * Mm + j) = make_float2(sl[r], sh[r]);

    float m0 = fmaxf(fmaxf(sl[0], sl[1]), fmaxf(sl[2], sl[3]));
    float m1 = fmaxf(fmaxf(sh[0], sh[1]), fmaxf(sh[2], sh[3]));
    float e0 = __expf(sl[0] - m0) + __expf(sl[1] - m0) + __expf(sl[2] - m0) + __expf(sl[3] - m0);
    float e1 = __expf(sh[0] - m1) + __expf(sh[1] - m1) + __expf(sh[2] - m1) + __expf(sh[3] - m1);

    const int g = rg * 2 + (rp4 >> 2);
    g_pm[(size_t)j * NGRP + g] = m0;
    g_pm[(size_t)(j + 1) * NGRP + g] = m1;
    g_ps[(size_t)j * NGRP + g] = e0;
    g_ps[(size_t)(j + 1) * NGRP + g] = e1;
}

// ===================== K2: combine 256 column partials (warp per column) =====================
__global__ __launch_bounds__(256) void k2_colcombine()
{
    const int w = threadIdx.x >> 5, lane = threadIdx.x & 31;
    const int j = blockIdx.x * 8 + w;
    const float4* pm = reinterpret_cast<const float4*>(g_pm + (size_t)j * NGRP);
    const float4* ps = reinterpret_cast<const float4*>(g_ps + (size_t)j * NGRP);

    float4 m4a = pm[lane * 2], m4b = pm[lane * 2 + 1];
    float m = fmaxf(fmaxf(fmaxf(m4a.x, m4a.y), fmaxf(m4a.z, m4a.w)),
                    fmaxf(fmaxf(m4b.x, m4b.y), fmaxf(m4b.z, m4b.w)));
    m = warpMax(m);

    float4 s4a = ps[lane * 2], s4b = ps[lane * 2 + 1];
    float s = s4a.x * __expf(m4a.x - m) + s4a.y * __expf(m4a.y - m) +
              s4a.z * __expf(m4a.z - m) + s4a.w * __expf(m4a.w - m) +
              s4b.x * __expf(m4b.x - m) + s4b.y * __expf(m4b.y - m) +
              s4b.z * __expf(m4b.z - m) + s4b.w * __expf(m4b.w - m);
    s = warpSum(s);

    if (lane == 0) { g_cm[j] = m; g_cinv[j] = 1.0f / s; }
}

// ===================== K3: warp-per-row final partials + last-block combine =====================
__global__ __launch_bounds__(256) void k3_rows(float* __restrict__ out)
{
    __shared__ float shn[8], shd[8];
    __shared__ u32 sh_last;
    const int t = threadIdx.x;
    const int w = t >> 5, lane = t & 31;
    const int i = blockIdx.x * 8 + w;
    const float4* row = reinterpret_cast<const float4*>(g_S + (size_t)i * Mm);

    float4 s[8];
    float m = -3.4e38f;
    #pragma unroll
    for (int q = 0; q < 8; ++q) {
        s[q] = row[q * 32 + lane];
        m = fmaxf(m, fmaxf(fmaxf(s[q].x, s[q].y), fmaxf(s[q].z, s[q].w)));
    }
    m = warpMax(m);

    float4 e[8];
    float rs = 0.f;
    #pragma unroll
    for (int q = 0; q < 8; ++q) {
        e[q].x = __expf(s[q].x - m); e[q].y = __expf(s[q].y - m);
        e[q].z = __expf(s[q].z - m); e[q].w = __expf(s[q].w - m);
        rs += e[q].x + e[q].y + e[q].z + e[q].w;
    }
    rs = warpSum(rs);
    const float rinv = 1.0f / rs;

    float num = 0.f, den = 0.f;
    #pragma unroll
    for (int q = 0; q < 8; ++q) {
        float4 cm = reinterpret_cast<const float4*>(g_cm)[q * 32 + lane];
        float4 ci = reinterpret_cast<const float4*>(g_cinv)[q * 32 + lane];
        {
            float a = e[q].x * rinv, b = __expf(s[q].x - cm.x) * ci.x;
            float u = a + b - a * b; num += u * s[q].x; den += u;
        }
        {
            float a = e[q].y * rinv, b = __expf(s[q].y - cm.y) * ci.y;
            float u = a + b - a * b; num += u * s[q].y; den += u;
        }
        {
            float a = e[q].z * rinv, b = __expf(s[q].z - cm.z) * ci.z;
            float u = a + b - a * b; num += u * s[q].z; den += u;
        }
        {
            float a = e[q].w * rinv, b = __expf(s[q].w - cm.w) * ci.w;
            float u = a + b - a * b; num += u * s[q].w; den += u;
        }
    }
    num = warpSum(num);
    den = warpSum(den);
    if (lane == 0) { g_num[i] = num; g_den[i] = den; }

    // ---- last-block deterministic combine ----
    __threadfence();
    __syncthreads();
    if (t == 0) sh_last = atomicAdd(&g_done, 1u);
    __syncthreads();
    if (sh_last != K3_BLOCKS - 1) return;

    __threadfence();   // acquire side: see all blocks' g_num/g_den
    float n2 = 0.f, d2 = 0.f;
    #pragma unroll
    for (int p = t; p < Nn; p += 256) { n2 += g_num[p]; d2 += g_den[p]; }
    n2 = warpSum(n2); d2 = warpSum(d2);
    if (lane == 0) { shn[w] = n2; shd[w] = d2; }
    __syncthreads();
    if (w == 0) {
        float n = (lane < 8) ? shn[lane] : 0.f;
        float d = (lane < 8) ? shd[lane] : 0.f;
        n = warpSum(n); d = warpSum(d);
        if (lane == 0) {
            out[0] = n / d;
            g_done = 0;          // self-reset for next graph replay
        }
    }
}

extern "C" void kernel_launch(void* const* d_in, const int* in_sizes, int n_in,
                              void* d_out, int out_size)
{
    const float* zx = (const float*)d_in[0];
    const float* zy = (const float*)d_in[1];
    float* out = (float*)d_out;

    k1_scores<<<(Nn / RG) * (Mm / CT), 128>>>(zx, zy);
    k2_colcombine<<<Mm / 8, 256>>>();
    k3_rows<<<K3_BLOCKS, 256>>>(out);
}